// round 12
// baseline (speedup 1.0000x reference)
#include <cuda_runtime.h>

#define NROWS 1024
#define EMB   256

// Grid: NROWS/2 row-pair CTAs (128 thr) + 1 count CTA. Barrier-free.
// Row CTA b: rows i0=2b, i1=2b+1 (adjacent; union segment [lo0,hi1) is
// contiguous since batch is sorted).
//   - bounds: 128-elem window, 1 int4/lane, ballots + popc thresholds for
//     both rows (second ballot set only if the pair straddles groups)
//   - zero: thread t covers cols [t*8,t*8+8) of both rows/both arrays,
//     skipping each row's own interior
//   - compute: warp-per-j over [lo0,hi1), xj loaded ONCE per j serving both
//     rows; 2-way j-unroll (4 accs); merge+butterfly reduce (lane0 -> i0,
//     lane1 -> i1); per-row segment/diagonal predication at store.
// Count CTA (bid == NROWS/2): 32-bin histogram; count = sum h^2 - N.
__global__ __launch_bounds__(128) void distmax_all(
    const float* __restrict__ xs, const int* __restrict__ batch,
    const float* __restrict__ w, const float* __restrict__ bptr,
    float* __restrict__ out_pred, float* __restrict__ out_mask,
    float* __restrict__ out_count)
{
    const int t    = threadIdx.x;
    const int lane = t & 31;
    const int wid  = t >> 5;
    const int bid  = blockIdx.x;

    // ---- count CTA ----
    if (bid == NROWS / 2) {
        __shared__ int h[32];
        if (t < 32) h[t] = 0;
        __syncthreads();
        #pragma unroll
        for (int k = 0; k < 2; k++) {
            int4 v = reinterpret_cast<const int4*>(batch)[t + k * 128];
            atomicAdd(&h[v.x], 1);
            atomicAdd(&h[v.y], 1);
            atomicAdd(&h[v.z], 1);
            atomicAdd(&h[v.w], 1);
        }
        __syncthreads();
        if (t < 32) {
            int c = h[t] * h[t];
            #pragma unroll
            for (int o = 16; o; o >>= 1) c += __shfl_xor_sync(0xffffffffu, c, o);
            if (t == 0) out_count[0] = (float)(c - NROWS);
        }
        return;
    }

    const int i0 = bid * 2;
    const int i1 = i0 + 1;

    // ---- window + ballot bounds for both rows ----
    int wbase = i0 - 64;
    if (wbase < 0) wbase = 0;
    wbase &= ~3;
    if (wbase > NROWS - 128) wbase = NROWS - 128;

    const int  bi0 = batch[i0];
    const int  bi1 = batch[i1];
    const int4 v   = reinterpret_cast<const int4*>(batch + wbase)[lane];

    unsigned ma[4], mb[4];
    ma[0] = __ballot_sync(0xffffffffu, v.x == bi0);
    ma[1] = __ballot_sync(0xffffffffu, v.y == bi0);
    ma[2] = __ballot_sync(0xffffffffu, v.z == bi0);
    ma[3] = __ballot_sync(0xffffffffu, v.w == bi0);
    if (bi1 == bi0) {
        mb[0] = ma[0]; mb[1] = ma[1]; mb[2] = ma[2]; mb[3] = ma[3];
    } else {
        mb[0] = __ballot_sync(0xffffffffu, v.x == bi1);
        mb[1] = __ballot_sync(0xffffffffu, v.y == bi1);
        mb[2] = __ballot_sync(0xffffffffu, v.z == bi1);
        mb[3] = __ballot_sync(0xffffffffu, v.w == bi1);
    }

    int nb0 = 0, na0 = 0, nb1 = 0, na1 = 0;
    const int d0 = i0 - wbase, d1 = i1 - wbase;
    #pragma unroll
    for (int c = 0; c < 4; c++) {
        // row 0 thresholds
        {
            const int nlt = (d0 - c + 3) >> 2;
            const int nle = (d0 >= c) ? (((d0 - c) >> 2) + 1) : 0;
            const unsigned ltm = (unsigned)((1ull << nlt) - 1ull);
            const unsigned lem = (unsigned)((1ull << nle) - 1ull);
            nb0 += __popc(ma[c] & ltm);
            na0 += __popc(ma[c] & ~lem);
        }
        // row 1 thresholds
        {
            const int nlt = (d1 - c + 3) >> 2;
            const int nle = (d1 >= c) ? (((d1 - c) >> 2) + 1) : 0;
            const unsigned ltm = (unsigned)((1ull << nlt) - 1ull);
            const unsigned lem = (unsigned)((1ull << nle) - 1ull);
            nb1 += __popc(mb[c] & ltm);
            na1 += __popc(mb[c] & ~lem);
        }
    }
    const int lo0 = i0 - nb0, hi0 = i0 + na0 + 1;
    const int lo1 = i1 - nb1, hi1 = i1 + na1 + 1;

    float* __restrict__ prow0 = out_pred + (size_t)i0 * NROWS;
    float* __restrict__ mrow0 = out_mask + (size_t)i0 * NROWS;
    float* __restrict__ prow1 = out_pred + (size_t)i1 * NROWS;
    float* __restrict__ mrow1 = out_mask + (size_t)i1 * NROWS;

    // ---- zero phase: thread t covers cols [t*8, t*8+8) of both rows ----
    {
        const float4 z = make_float4(0.f, 0.f, 0.f, 0.f);
        #pragma unroll
        for (int half = 0; half < 2; half++) {
            const int c0 = t * 8 + half * 4;
            // row 0
            if (c0 + 4 <= lo0 || c0 >= hi0) {
                reinterpret_cast<float4*>(prow0)[c0 >> 2] = z;
                reinterpret_cast<float4*>(mrow0)[c0 >> 2] = z;
            } else if (c0 < lo0 || c0 + 4 > hi0) {
                #pragma unroll
                for (int e = 0; e < 4; e++) {
                    const int c = c0 + e;
                    if (c < lo0 || c >= hi0) { prow0[c] = 0.f; mrow0[c] = 0.f; }
                }
            }
            // row 1
            if (c0 + 4 <= lo1 || c0 >= hi1) {
                reinterpret_cast<float4*>(prow1)[c0 >> 2] = z;
                reinterpret_cast<float4*>(mrow1)[c0 >> 2] = z;
            } else if (c0 < lo1 || c0 + 4 > hi1) {
                #pragma unroll
                for (int e = 0; e < 4; e++) {
                    const int c = c0 + e;
                    if (c < lo1 || c >= hi1) { prow1[c] = 0.f; mrow1[c] = 0.f; }
                }
            }
        }
    }

    // ---- compute: warp-per-j over union [lo0, hi1), xj shared by 2 rows ----
    const float bias = __ldg(bptr);
    const float4* w4 = reinterpret_cast<const float4*>(w);
    const float4 w0  = w4[lane], w1 = w4[32 + lane];
    const float4* xia = reinterpret_cast<const float4*>(xs + (size_t)i0 * EMB);
    const float4* xib = reinterpret_cast<const float4*>(xs + (size_t)i1 * EMB);
    const float4 xa0 = xia[lane], xa1 = xia[32 + lane];
    const float4 xb0 = xib[lane], xb1 = xib[32 + lane];

    for (int jb = lo0 + wid; jb < hi1; jb += 8) {
        const int  j0 = jb, j1 = jb + 4;
        const bool p1 = (j1 < hi1);

        float a00 = 0.f, a10 = 0.f, a01 = 0.f, a11 = 0.f;  // a{row}{jslot}
        {
            const float4* xj = reinterpret_cast<const float4*>(xs + (size_t)j0 * EMB);
            const float4 c0 = xj[lane], c1 = xj[32 + lane];
            a00 = fmaf(fmaxf(xa0.x, c0.x), w0.x, fmaf(fmaxf(xa0.y, c0.y), w0.y,
                  fmaf(fmaxf(xa0.z, c0.z), w0.z, fmaf(fmaxf(xa0.w, c0.w), w0.w,
                  fmaf(fmaxf(xa1.x, c1.x), w1.x, fmaf(fmaxf(xa1.y, c1.y), w1.y,
                  fmaf(fmaxf(xa1.z, c1.z), w1.z, fmaxf(xa1.w, c1.w) * w1.w)))))));
            a10 = fmaf(fmaxf(xb0.x, c0.x), w0.x, fmaf(fmaxf(xb0.y, c0.y), w0.y,
                  fmaf(fmaxf(xb0.z, c0.z), w0.z, fmaf(fmaxf(xb0.w, c0.w), w0.w,
                  fmaf(fmaxf(xb1.x, c1.x), w1.x, fmaf(fmaxf(xb1.y, c1.y), w1.y,
                  fmaf(fmaxf(xb1.z, c1.z), w1.z, fmaxf(xb1.w, c1.w) * w1.w)))))));
        }
        if (p1) {
            const float4* xj = reinterpret_cast<const float4*>(xs + (size_t)j1 * EMB);
            const float4 c0 = xj[lane], c1 = xj[32 + lane];
            a01 = fmaf(fmaxf(xa0.x, c0.x), w0.x, fmaf(fmaxf(xa0.y, c0.y), w0.y,
                  fmaf(fmaxf(xa0.z, c0.z), w0.z, fmaf(fmaxf(xa0.w, c0.w), w0.w,
                  fmaf(fmaxf(xa1.x, c1.x), w1.x, fmaf(fmaxf(xa1.y, c1.y), w1.y,
                  fmaf(fmaxf(xa1.z, c1.z), w1.z, fmaxf(xa1.w, c1.w) * w1.w)))))));
            a11 = fmaf(fmaxf(xb0.x, c0.x), w0.x, fmaf(fmaxf(xb0.y, c0.y), w0.y,
                  fmaf(fmaxf(xb0.z, c0.z), w0.z, fmaf(fmaxf(xb0.w, c0.w), w0.w,
                  fmaf(fmaxf(xb1.x, c1.x), w1.x, fmaf(fmaxf(xb1.y, c1.y), w1.y,
                  fmaf(fmaxf(xb1.z, c1.z), w1.z, fmaxf(xb1.w, c1.w) * w1.w)))))));
        }

        // merge rows into even/odd lanes, then butterfly over remaining bits.
        const bool odd = lane & 1;
        float u0 = odd ? a10 : a00;
        float y0 = odd ? a00 : a10;
        float u1 = odd ? a11 : a01;
        float y1 = odd ? a01 : a11;
        u0 += __shfl_xor_sync(0xffffffffu, y0, 1);
        u1 += __shfl_xor_sync(0xffffffffu, y1, 1);
        #pragma unroll
        for (int o = 16; o > 1; o >>= 1) {
            u0 += __shfl_xor_sync(0xffffffffu, u0, o);
            u1 += __shfl_xor_sync(0xffffffffu, u1, o);
        }
        // lane 0: row i0 result; lane 1: row i1 result (for j0 / j1).

        if (lane < 2) {
            const int  irow = odd ? i1 : i0;
            const int  rlo  = odd ? lo1 : lo0;
            const int  rhi  = odd ? hi1 : hi0;
            float* __restrict__ pr = odd ? prow1 : prow0;
            float* __restrict__ mr = odd ? mrow1 : mrow0;
            if (j0 >= rlo && j0 < rhi) {
                pr[j0] = (j0 == irow) ? 0.f : fmaxf(u0 + bias, 0.f);
                mr[j0] = (j0 == irow) ? 0.f : 1.f;
            }
            if (p1 && j1 >= rlo && j1 < rhi) {
                pr[j1] = (j1 == irow) ? 0.f : fmaxf(u1 + bias, 0.f);
                mr[j1] = (j1 == irow) ? 0.f : 1.f;
            }
        }
    }
}

extern "C" void kernel_launch(void* const* d_in, const int* in_sizes, int n_in,
                              void* d_out, int out_size)
{
    const float* xs    = (const float*)d_in[0];  // [1024, 256] f32
    const int*   batch = (const int*)d_in[1];    // [1024] int32 (sorted, ids in [0,32))
    const float* w     = (const float*)d_in[2];  // [256] f32
    const float* b     = (const float*)d_in[3];  // [1] f32

    float* out       = (float*)d_out;
    float* out_pred  = out;                              // [1024*1024]
    float* out_mask  = out + (size_t)NROWS * NROWS;      // [1024*1024]
    float* out_count = out + 2 * (size_t)NROWS * NROWS;  // [1]

    distmax_all<<<NROWS / 2 + 1, 128>>>(xs, batch, w, b, out_pred, out_mask, out_count);
}

// round 13
// speedup vs baseline: 1.1965x; 1.1965x over previous
#include <cuda_runtime.h>
#include <cstdint>

#define NROWS 1024
#define EMB   256

// One CTA (128 thr) per row + 1 count CTA. Output rows are assembled in SMEM
// (zeros + computed interior + mask) and written with TWO cp.async.bulk S2G
// copies per row (4KB each) instead of ~512 STG.128 — removing the per-element
// store-issue floor (~12 cyc/STG.128) that capped every previous variant.
// Row CTA:
//   - bounds [lo,hi): 128-elem window, 1 int4/lane, ballots + popc (per warp)
//   - zero 8KB smem (pred row + mask row), __syncthreads
//   - compute interior warp-per-j (4 streams, 4-way unroll, coalesced
//     LDG.128, 5-step shfl), lane0 STS pred/mask (diagonal = 0)
//   - __syncthreads, fence.proxy.async, tid0: 2 bulk stores + commit + wait
// Count CTA (bid == NROWS): 32-bin histogram; count = sum h^2 - N.
__global__ __launch_bounds__(128) void distmax_all(
    const float* __restrict__ xs, const int* __restrict__ batch,
    const float* __restrict__ w, const float* __restrict__ bptr,
    float* __restrict__ out_pred, float* __restrict__ out_mask,
    float* __restrict__ out_count)
{
    const int t    = threadIdx.x;
    const int lane = t & 31;
    const int wid  = t >> 5;
    const int bid  = blockIdx.x;

    // ---- count CTA ----
    if (bid == NROWS) {
        __shared__ int h[32];
        if (t < 32) h[t] = 0;
        __syncthreads();
        #pragma unroll
        for (int k = 0; k < 2; k++) {
            int4 v = reinterpret_cast<const int4*>(batch)[t + k * 128];
            atomicAdd(&h[v.x], 1);
            atomicAdd(&h[v.y], 1);
            atomicAdd(&h[v.z], 1);
            atomicAdd(&h[v.w], 1);
        }
        __syncthreads();
        if (t < 32) {
            int c = h[t] * h[t];
            #pragma unroll
            for (int o = 16; o; o >>= 1) c += __shfl_xor_sync(0xffffffffu, c, o);
            if (t == 0) out_count[0] = (float)(c - NROWS);
        }
        return;
    }

    // [0, NROWS): pred row;  [NROWS, 2*NROWS): mask row
    __shared__ __align__(16) float s_row[2 * NROWS];

    const int i = bid;

    // ---- prefetch independent loads ----
    int wbase = i - 64;
    if (wbase < 0) wbase = 0;
    wbase &= ~3;
    if (wbase > NROWS - 128) wbase = NROWS - 128;

    const int  bi = batch[i];
    const int4 v  = reinterpret_cast<const int4*>(batch + wbase)[lane];

    const float4* xi4 = reinterpret_cast<const float4*>(xs + (size_t)i * EMB);
    const float4* w4  = reinterpret_cast<const float4*>(w);
    const float4 xi0 = xi4[lane], xi1 = xi4[32 + lane];
    const float4 w0  = w4 [lane], w1  = w4 [32 + lane];
    const float bias = __ldg(bptr);

    // ---- ballot bounds (each warp computes the same uniform result) ----
    const int d = i - wbase;
    const unsigned m0 = __ballot_sync(0xffffffffu, v.x == bi);
    const unsigned m1 = __ballot_sync(0xffffffffu, v.y == bi);
    const unsigned m2 = __ballot_sync(0xffffffffu, v.z == bi);
    const unsigned m3 = __ballot_sync(0xffffffffu, v.w == bi);

    int nbefore = 0, nafter = 0;
    {
        const unsigned m[4] = {m0, m1, m2, m3};
        #pragma unroll
        for (int c = 0; c < 4; c++) {
            const int nlt = (d - c + 3) >> 2;
            const int nle = (d >= c) ? (((d - c) >> 2) + 1) : 0;
            const unsigned ltm = (unsigned)((1ull << nlt) - 1ull);
            const unsigned lem = (unsigned)((1ull << nle) - 1ull);
            nbefore += __popc(m[c] & ltm);
            nafter  += __popc(m[c] & ~lem);
        }
    }
    const int lo = i - nbefore;
    const int hi = i + nafter + 1;

    // ---- zero both smem rows: 512 float4 / 128 threads = 4 each ----
    {
        float4* s4 = reinterpret_cast<float4*>(s_row);
        const float4 z = make_float4(0.f, 0.f, 0.f, 0.f);
        s4[t]       = z;
        s4[t + 128] = z;
        s4[t + 256] = z;
        s4[t + 384] = z;
    }
    __syncthreads();

    // ---- compute interior into smem: warp-per-j, 4 streams, 4-way unroll ----
    for (int jb = lo + wid; jb < hi; jb += 16) {
        const int j0 = jb, j1 = jb + 4, j2 = jb + 8, j3 = jb + 12;
        const bool p1 = (j1 < hi), p2 = (j2 < hi), p3 = (j3 < hi);

        float acc0 = 0.f, acc1 = 0.f, acc2 = 0.f, acc3 = 0.f;
        {
            const float4* xj = reinterpret_cast<const float4*>(xs + (size_t)j0 * EMB);
            const float4 a = xj[lane], b = xj[32 + lane];
            acc0 = fmaf(fmaxf(xi0.x, a.x), w0.x, fmaf(fmaxf(xi0.y, a.y), w0.y,
                   fmaf(fmaxf(xi0.z, a.z), w0.z, fmaf(fmaxf(xi0.w, a.w), w0.w,
                   fmaf(fmaxf(xi1.x, b.x), w1.x, fmaf(fmaxf(xi1.y, b.y), w1.y,
                   fmaf(fmaxf(xi1.z, b.z), w1.z, fmaxf(xi1.w, b.w) * w1.w)))))));
        }
        if (p1) {
            const float4* xj = reinterpret_cast<const float4*>(xs + (size_t)j1 * EMB);
            const float4 a = xj[lane], b = xj[32 + lane];
            acc1 = fmaf(fmaxf(xi0.x, a.x), w0.x, fmaf(fmaxf(xi0.y, a.y), w0.y,
                   fmaf(fmaxf(xi0.z, a.z), w0.z, fmaf(fmaxf(xi0.w, a.w), w0.w,
                   fmaf(fmaxf(xi1.x, b.x), w1.x, fmaf(fmaxf(xi1.y, b.y), w1.y,
                   fmaf(fmaxf(xi1.z, b.z), w1.z, fmaxf(xi1.w, b.w) * w1.w)))))));
        }
        if (p2) {
            const float4* xj = reinterpret_cast<const float4*>(xs + (size_t)j2 * EMB);
            const float4 a = xj[lane], b = xj[32 + lane];
            acc2 = fmaf(fmaxf(xi0.x, a.x), w0.x, fmaf(fmaxf(xi0.y, a.y), w0.y,
                   fmaf(fmaxf(xi0.z, a.z), w0.z, fmaf(fmaxf(xi0.w, a.w), w0.w,
                   fmaf(fmaxf(xi1.x, b.x), w1.x, fmaf(fmaxf(xi1.y, b.y), w1.y,
                   fmaf(fmaxf(xi1.z, b.z), w1.z, fmaxf(xi1.w, b.w) * w1.w)))))));
        }
        if (p3) {
            const float4* xj = reinterpret_cast<const float4*>(xs + (size_t)j3 * EMB);
            const float4 a = xj[lane], b = xj[32 + lane];
            acc3 = fmaf(fmaxf(xi0.x, a.x), w0.x, fmaf(fmaxf(xi0.y, a.y), w0.y,
                   fmaf(fmaxf(xi0.z, a.z), w0.z, fmaf(fmaxf(xi0.w, a.w), w0.w,
                   fmaf(fmaxf(xi1.x, b.x), w1.x, fmaf(fmaxf(xi1.y, b.y), w1.y,
                   fmaf(fmaxf(xi1.z, b.z), w1.z, fmaxf(xi1.w, b.w) * w1.w)))))));
        }

        #pragma unroll
        for (int o = 16; o; o >>= 1) {
            acc0 += __shfl_xor_sync(0xffffffffu, acc0, o);
            acc1 += __shfl_xor_sync(0xffffffffu, acc1, o);
            acc2 += __shfl_xor_sync(0xffffffffu, acc2, o);
            acc3 += __shfl_xor_sync(0xffffffffu, acc3, o);
        }

        if (lane == 0) {
            s_row[j0]         = (j0 == i) ? 0.f : fmaxf(acc0 + bias, 0.f);
            s_row[NROWS + j0] = (j0 == i) ? 0.f : 1.f;
            if (p1) { s_row[j1]         = (j1 == i) ? 0.f : fmaxf(acc1 + bias, 0.f);
                      s_row[NROWS + j1] = (j1 == i) ? 0.f : 1.f; }
            if (p2) { s_row[j2]         = (j2 == i) ? 0.f : fmaxf(acc2 + bias, 0.f);
                      s_row[NROWS + j2] = (j2 == i) ? 0.f : 1.f; }
            if (p3) { s_row[j3]         = (j3 == i) ? 0.f : fmaxf(acc3 + bias, 0.f);
                      s_row[NROWS + j3] = (j3 == i) ? 0.f : 1.f; }
        }
    }

    __syncthreads();

    // ---- bulk store both rows: 2 x 4KB SMEM -> GMEM via TMA bulk path ----
    if (t == 0) {
        asm volatile("fence.proxy.async.shared::cta;" ::: "memory");
        uint32_t saddr = (uint32_t)__cvta_generic_to_shared(s_row);
        float* gp = out_pred + (size_t)i * NROWS;
        float* gm = out_mask + (size_t)i * NROWS;
        asm volatile("cp.async.bulk.global.shared::cta.bulk_group [%0], [%1], %2;"
                     :: "l"(gp), "r"(saddr), "r"(4096u) : "memory");
        asm volatile("cp.async.bulk.global.shared::cta.bulk_group [%0], [%1], %2;"
                     :: "l"(gm), "r"(saddr + 4096u), "r"(4096u) : "memory");
        asm volatile("cp.async.bulk.commit_group;" ::: "memory");
        asm volatile("cp.async.bulk.wait_group 0;" ::: "memory");
    }
}

extern "C" void kernel_launch(void* const* d_in, const int* in_sizes, int n_in,
                              void* d_out, int out_size)
{
    const float* xs    = (const float*)d_in[0];  // [1024, 256] f32
    const int*   batch = (const int*)d_in[1];    // [1024] int32 (sorted, ids in [0,32))
    const float* w     = (const float*)d_in[2];  // [256] f32
    const float* b     = (const float*)d_in[3];  // [1] f32

    float* out       = (float*)d_out;
    float* out_pred  = out;                              // [1024*1024]
    float* out_mask  = out + (size_t)NROWS * NROWS;      // [1024*1024]
    float* out_count = out + 2 * (size_t)NROWS * NROWS;  // [1]

    distmax_all<<<NROWS + 1, 128>>>(xs, batch, w, b, out_pred, out_mask, out_count);
}